// round 3
// baseline (speedup 1.0000x reference)
#include <cuda_runtime.h>
#include <cuda_bf16.h>
#include <math.h>

#define NE 32768
#define NSTEP 65535   // 2*NE - 1

// ---------------- device scratch (static, no allocation) ----------------
__device__ __align__(16) float g_encp[NE * 200];      // projected encodings (h|c)
__device__ __align__(16) float g_PC[NE * 640];        // [0..500)=P row, [512..612)=c_e, padded
__device__ __align__(16) float g_X[NE * 200];         // merge chain states (h|c)
__device__ __align__(16) float g_WtProj[768 * 200];   // W_proj transposed
__device__ __align__(16) float g_WtE[100 * 500];      // W_tree[:,100:200] transposed
__device__ __align__(16) float g_WL[600 * 24];        // concat loss weights, [col][out]
__device__ float g_bL[24];
__device__ float g_losses[NSTEP];

__device__ __forceinline__ float sigf(float x)  { return 1.f / (1.f + __expf(-x)); }
__device__ __forceinline__ float tanh_f(float x){ return 1.f - 2.f / (__expf(2.f * x) + 1.f); }

#define FMA2(acc, a, b) asm("fma.rn.f32x2 %0, %1, %2, %0;" : "+l"(acc) : "l"(a), "l"(b))

// ---------------- prep: transposes / packing ----------------
__global__ void prep_kernel(const float* __restrict__ Wproj,
                            const float* __restrict__ Wtree,
                            const float* __restrict__ Wact,
                            const float* __restrict__ Wlab,
                            const float* __restrict__ Wdir,
                            const float* __restrict__ bact,
                            const float* __restrict__ blab,
                            const float* __restrict__ bdir) {
    int i = blockIdx.x * blockDim.x + threadIdx.x;
    int stride = gridDim.x * blockDim.x;
    for (int e = i; e < 768 * 200; e += stride) {
        int k = e / 200, j = e % 200;
        g_WtProj[e] = Wproj[j * 768 + k];
    }
    for (int e = i; e < 100 * 500; e += stride) {
        int c = e / 500, r = e % 500;
        g_WtE[e] = Wtree[r * 200 + 100 + c];
    }
    for (int e = i; e < 600 * 24; e += stride) {
        int c = e / 24, q = e % 24;
        float v;
        if (q < 2)       v = Wact[q * 600 + c];
        else if (q < 21) v = Wlab[(q - 2) * 600 + c];
        else             v = Wdir[(q - 21) * 600 + c];
        g_WL[e] = v;
    }
    if (i < 24) {
        g_bL[i] = (i < 2) ? bact[i] : (i < 21) ? blab[i - 2] : bdir[i - 21];
    }
}

// ---------------- generic fp32 GEMM: C[M,N] = A[M,lda] * B[K,N] + bias ----------------
__global__ void gemm_kernel(const float* __restrict__ A, int lda,
                            const float* __restrict__ B,
                            const float* __restrict__ bias,
                            float* __restrict__ C, int ldc,
                            int N, int K) {
    __shared__ float As[16][68];
    __shared__ float Bs[16][64];
    int m0 = blockIdx.y * 64;
    int n0 = blockIdx.x * 64;
    int tid = threadIdx.x;
    int r0 = (tid >> 3) * 4;
    int c0 = (tid & 7) * 8;
    float acc[4][8];
    #pragma unroll
    for (int i = 0; i < 4; i++)
        #pragma unroll
        for (int j = 0; j < 8; j++) acc[i][j] = 0.f;

    for (int k0 = 0; k0 < K; k0 += 16) {
        #pragma unroll
        for (int i = 0; i < 8; i++) {
            int e = tid + 128 * i;
            int m = e >> 4, k = e & 15;
            As[k][m] = (k0 + k < K) ? A[(m0 + m) * lda + k0 + k] : 0.f;
        }
        #pragma unroll
        for (int i = 0; i < 8; i++) {
            int e = tid + 128 * i;
            int k = e >> 6, n = e & 63;
            float v = 0.f;
            if (k0 + k < K && n0 + n < N) v = B[(k0 + k) * N + n0 + n];
            Bs[k][n] = v;
        }
        __syncthreads();
        #pragma unroll
        for (int kk = 0; kk < 16; kk++) {
            float a[4];
            #pragma unroll
            for (int i = 0; i < 4; i++) a[i] = As[kk][r0 + i];
            float4 b0 = *(const float4*)&Bs[kk][c0];
            float4 b1 = *(const float4*)&Bs[kk][c0 + 4];
            float b[8] = {b0.x, b0.y, b0.z, b0.w, b1.x, b1.y, b1.z, b1.w};
            #pragma unroll
            for (int i = 0; i < 4; i++)
                #pragma unroll
                for (int j = 0; j < 8; j++) acc[i][j] += a[i] * b[j];
        }
        __syncthreads();
    }
    #pragma unroll
    for (int i = 0; i < 4; i++) {
        int m = m0 + r0 + i;
        #pragma unroll
        for (int j = 0; j < 8; j++) {
            int n = n0 + c0 + j;
            if (n < N) C[m * ldc + n] = acc[i][j] + bias[n];
        }
    }
}

// ---------------- copy c_e into the packed PC rows ----------------
__global__ void copyc_kernel() {
    int i = blockIdx.x * blockDim.x + threadIdx.x;
    int stride = gridDim.x * blockDim.x;
    for (int e = i; e < NE * 25; e += stride) {
        int m = e / 25, q = e % 25;
        const float4* src = (const float4*)(g_encp + (size_t)m * 200 + 100);
        float4* dst = (float4*)(g_PC + (size_t)m * 640 + 512);
        dst[q] = src[q];
    }
}

// ---------------- sequential TreeLSTM chain (single CTA, pipelined) ----------------
// hs layout: h[0..50) at floats [0..50), h[50..100) at floats [52..102)  (16B-aligned halves)
// Threads 0..999: matvec (2 threads/row, 12 LDS.128 + 1 LDS.64 each, f32x2 FMA).
// Threads 1000..1023: cp.async prefetch of PC row m+2 into 3-slot SMEM ring.
__global__ void __launch_bounds__(1024, 1) chain_kernel(const float* __restrict__ Wtree) {
    __shared__ __align__(16) float hs[104];
    __shared__ __align__(16) float gs[512];
    __shared__ __align__(16) float psm[3][640];
    int tid = threadIdx.x;
    int r = tid >> 1, half = tid & 1;

    // pack 25 x f32x2 weights (cols [half*50, half*50+50) of row r)
    unsigned long long w2[25];
    if (tid < 1000) {
        const float* wb = Wtree + r * 200 + half * 50;
        #pragma unroll
        for (int c = 0; c < 25; c++) {
            float lo = wb[2 * c], hi = wb[2 * c + 1];
            w2[c] = ((unsigned long long)__float_as_uint(hi) << 32) | __float_as_uint(lo);
        }
    } else {
        #pragma unroll
        for (int c = 0; c < 25; c++) w2[c] = 0ull;
    }

    float cprev = 0.f;
    if (tid < 100) {
        float h0 = g_encp[tid];
        cprev = g_encp[100 + tid];
        hs[tid + (tid >= 50 ? 2 : 0)] = h0;
        g_X[tid] = h0;
        g_X[100 + tid] = cprev;
    }

    // prologue: prefetch PC rows 1 and 2
    if (tid >= 1000) {
        int p = tid - 1000;
        #pragma unroll
        for (int s = 1; s <= 2; s++) {
            const float4* src = (const float4*)(g_PC + (size_t)s * 640);
            unsigned sdst = (unsigned)__cvta_generic_to_shared(&psm[s % 3][0]);
            for (int k = p; k < 160; k += 24) {
                asm volatile("cp.async.cg.shared.global [%0], [%1], 16;\n"
                             :: "r"(sdst + k * 16), "l"(src + k) : "memory");
            }
            asm volatile("cp.async.commit_group;\n" ::: "memory");
        }
    }
    __syncthreads();

    for (int m = 1; m <= NE - 2; m++) {
        if (tid >= 1000) {
            int p = tid - 1000;
            int mp = m + 2;
            if (mp < NE) {
                const float4* src = (const float4*)(g_PC + (size_t)mp * 640);
                unsigned sdst = (unsigned)__cvta_generic_to_shared(&psm[mp % 3][0]);
                for (int k = p; k < 160; k += 24) {
                    asm volatile("cp.async.cg.shared.global [%0], [%1], 16;\n"
                                 :: "r"(sdst + k * 16), "l"(src + k) : "memory");
                }
            }
            asm volatile("cp.async.commit_group;\n" ::: "memory");
            asm volatile("cp.async.wait_group 2;\n" ::: "memory");
        } else {
            const float* hb = hs + (half ? 52 : 0);
            unsigned long long a0 = 0ull, a1 = 0ull;
            #pragma unroll
            for (int c = 0; c < 12; c++) {
                ulonglong2 hv = *(const ulonglong2*)(hb + 4 * c);
                FMA2(a0, w2[2 * c], hv.x);
                FMA2(a1, w2[2 * c + 1], hv.y);
            }
            {
                unsigned long long hv = *(const unsigned long long*)(hb + 48);
                FMA2(a0, w2[24], hv);
            }
            unsigned lo0 = (unsigned)a0, hi0 = (unsigned)(a0 >> 32);
            unsigned lo1 = (unsigned)a1, hi1 = (unsigned)(a1 >> 32);
            float acc = (__uint_as_float(lo0) + __uint_as_float(hi0)) +
                        (__uint_as_float(lo1) + __uint_as_float(hi1));
            unsigned mask = (tid < 992) ? 0xffffffffu : 0x000000ffu;
            acc += __shfl_xor_sync(mask, acc, 1);
            if (half == 0) gs[r] = acc;
        }
        __syncthreads();
        if (tid < 100) {
            const float* P = psm[m % 3];
            float gi  = gs[tid]       + P[tid];
            float gf1 = gs[100 + tid] + P[100 + tid];
            float gf2 = gs[200 + tid] + P[200 + tid];
            float go  = gs[300 + tid] + P[300 + tid];
            float gu  = gs[400 + tid] + P[400 + tid];
            float ce2 = P[512 + tid];
            float cc = sigf(gi) * tanh_f(gu) + sigf(gf1) * cprev + sigf(gf2) * ce2;
            float hh = sigf(go) * tanh_f(cc);
            cprev = cc;
            hs[tid + (tid >= 50 ? 2 : 0)] = hh;
            float* Xm = g_X + (size_t)m * 200;
            Xm[tid] = hh;
            Xm[100 + tid] = cc;
        }
        __syncthreads();
    }
}

// ---------------- per-step losses (parallel) ----------------
__device__ __forceinline__ float ce_all(const float* l, int a, int lb, int dr) {
    float m0 = fmaxf(l[0], l[1]);
    float loss = m0 + __logf(__expf(l[0] - m0) + __expf(l[1] - m0)) - l[a];
    float m1 = l[2];
    #pragma unroll
    for (int q = 3; q < 21; q++) m1 = fmaxf(m1, l[q]);
    float s1 = 0.f;
    #pragma unroll
    for (int q = 2; q < 21; q++) s1 += __expf(l[q] - m1);
    loss += m1 + __logf(s1) - l[2 + lb];
    float m2 = fmaxf(fmaxf(l[21], l[22]), l[23]);
    float s2 = __expf(l[21] - m2) + __expf(l[22] - m2) + __expf(l[23] - m2);
    loss += m2 + __logf(s2) - l[21 + dr];
    return loss;
}

__global__ void loss_kernel(const float* __restrict__ missing,
                            const int* __restrict__ ga,
                            const int* __restrict__ gl,
                            const int* __restrict__ gd) {
    __shared__ float fs[16][600];
    int t0 = blockIdx.x * 16;
    int tid = threadIdx.x;

    for (int e = tid; e < 16 * 600; e += 256) {
        int s = e / 600, c = e % 600;
        int t = t0 + s;
        float v = 0.f;
        if (t < NSTEP) {
            const float* src;
            int base;
            if (c < 200) {          // s1
                base = 0;
                if ((t & 1) == 0 && t >= 2) src = g_X + (size_t)(t / 2 - 1) * 200;
                else                         src = missing;
            } else if (c < 400) {   // s0
                base = 200;
                if (t & 1)       src = g_X + (size_t)(t / 2) * 200;
                else             src = (t == 0) ? missing : (g_encp + (size_t)(t / 2) * 200);
            } else {                // b
                base = 400;
                if (t == 0) src = g_encp;
                else {
                    int idx = t / 2 + 1;
                    src = (idx < NE) ? (g_encp + (size_t)idx * 200) : missing;
                }
            }
            v = src[c - base];
        }
        fs[s][c] = v;
    }
    __syncthreads();

    int warp = tid >> 5, lane = tid & 31;
    const float* f0 = fs[warp * 2];
    const float* f1 = fs[warp * 2 + 1];
    float acc0[24], acc1[24];
    #pragma unroll
    for (int q = 0; q < 24; q++) { acc0[q] = 0.f; acc1[q] = 0.f; }

    for (int c = lane; c < 600; c += 32) {
        float fa = f0[c], fb = f1[c];
        const float4* wp = (const float4*)(g_WL + c * 24);
        #pragma unroll
        for (int v4 = 0; v4 < 6; v4++) {
            float4 wv = wp[v4];
            acc0[v4 * 4 + 0] += wv.x * fa;  acc1[v4 * 4 + 0] += wv.x * fb;
            acc0[v4 * 4 + 1] += wv.y * fa;  acc1[v4 * 4 + 1] += wv.y * fb;
            acc0[v4 * 4 + 2] += wv.z * fa;  acc1[v4 * 4 + 2] += wv.z * fb;
            acc0[v4 * 4 + 3] += wv.w * fa;  acc1[v4 * 4 + 3] += wv.w * fb;
        }
    }
    #pragma unroll
    for (int off = 16; off; off >>= 1) {
        #pragma unroll
        for (int q = 0; q < 24; q++) {
            acc0[q] += __shfl_xor_sync(0xffffffffu, acc0[q], off);
            acc1[q] += __shfl_xor_sync(0xffffffffu, acc1[q], off);
        }
    }
    if (lane == 0) {
        int ta = t0 + warp * 2;
        if (ta < NSTEP) {
            float l[24];
            #pragma unroll
            for (int q = 0; q < 24; q++) l[q] = acc0[q] + g_bL[q];
            g_losses[ta] = ce_all(l, ga[ta], gl[ta], gd[ta]);
        }
        int tb = ta + 1;
        if (tb < NSTEP) {
            float l[24];
            #pragma unroll
            for (int q = 0; q < 24; q++) l[q] = acc1[q] + g_bL[q];
            g_losses[tb] = ce_all(l, ga[tb], gl[tb], gd[tb]);
        }
    }
}

// ---------------- deterministic final reduction ----------------
__global__ void reduce_kernel(float* __restrict__ out) {
    __shared__ float ss[1024];
    float s = 0.f;
    for (int i = threadIdx.x; i < NSTEP; i += 1024) s += g_losses[i];
    ss[threadIdx.x] = s;
    __syncthreads();
    for (int o = 512; o; o >>= 1) {
        if (threadIdx.x < o) ss[threadIdx.x] += ss[threadIdx.x + o];
        __syncthreads();
    }
    if (threadIdx.x == 0) out[0] = ss[0];
}

// ---------------- launch ----------------
extern "C" void kernel_launch(void* const* d_in, const int* in_sizes, int n_in,
                              void* d_out, int out_size) {
    const float* enc_cls = (const float*)d_in[0];
    const float* W_proj  = (const float*)d_in[1];
    const float* b_proj  = (const float*)d_in[2];
    const float* missing = (const float*)d_in[3];
    const float* W_act   = (const float*)d_in[4];
    const float* b_act   = (const float*)d_in[5];
    const float* W_lab   = (const float*)d_in[6];
    const float* b_lab   = (const float*)d_in[7];
    const float* W_dir   = (const float*)d_in[8];
    const float* b_dir   = (const float*)d_in[9];
    const float* W_tree  = (const float*)d_in[10];
    const float* b_tree  = (const float*)d_in[11];
    const int*   ga      = (const int*)d_in[12];
    const int*   gl      = (const int*)d_in[13];
    const int*   gd      = (const int*)d_in[14];

    void *p_encp, *p_PC, *p_WtProj, *p_WtE;
    cudaGetSymbolAddress(&p_encp, g_encp);
    cudaGetSymbolAddress(&p_PC, g_PC);
    cudaGetSymbolAddress(&p_WtProj, g_WtProj);
    cudaGetSymbolAddress(&p_WtE, g_WtE);

    prep_kernel<<<128, 256>>>(W_proj, W_tree, W_act, W_lab, W_dir, b_act, b_lab, b_dir);

    // enc_proj = enc_cls @ W_proj^T + b_proj   (M=32768, N=200, K=768)
    gemm_kernel<<<dim3(4, 512), 128>>>(enc_cls, 768, (const float*)p_WtProj,
                                       b_proj, (float*)p_encp, 200, 200, 768);

    // P = enc_proj[:, :100] @ W_e^T + b_tree   (M=32768, N=500, K=100) -> packed rows
    gemm_kernel<<<dim3(8, 512), 128>>>((const float*)p_encp, 200, (const float*)p_WtE,
                                       b_tree, (float*)p_PC, 640, 500, 100);

    copyc_kernel<<<256, 256>>>();

    chain_kernel<<<1, 1024>>>(W_tree);

    loss_kernel<<<4096, 256>>>(missing, ga, gl, gd);

    reduce_kernel<<<1, 1024>>>((float*)d_out);
}

// round 4
// speedup vs baseline: 1.5031x; 1.5031x over previous
#include <cuda_runtime.h>
#include <cuda_bf16.h>
#include <math.h>

#define NE 32768
#define NSTEP 65535   // 2*NE - 1

// ---------------- device scratch (static, no allocation) ----------------
__device__ __align__(16) float g_encp[NE * 200];      // projected encodings (h|c)
__device__ __align__(16) float g_PC[NE * 640];        // [0..500)=P row, [512..612)=c_e, padded
__device__ __align__(16) float g_X[NE * 200];         // merge chain states (h|c)
__device__ __align__(16) float g_WtProj[768 * 200];   // W_proj transposed
__device__ __align__(16) float g_WtE[100 * 500];      // W_tree[:,100:200] transposed
__device__ __align__(16) float g_WL[600 * 24];        // concat loss weights, [col][out]
__device__ float g_bL[24];
__device__ float g_losses[NSTEP];

__device__ __forceinline__ float sig_t(float x)  { return 0.5f * __tanhf(0.5f * x) + 0.5f; }

#define FMA2(acc, a, b) asm("fma.rn.f32x2 %0, %1, %2, %0;" : "+l"(acc) : "l"(a), "l"(b))

// ---------------- prep: transposes / packing ----------------
__global__ void prep_kernel(const float* __restrict__ Wproj,
                            const float* __restrict__ Wtree,
                            const float* __restrict__ Wact,
                            const float* __restrict__ Wlab,
                            const float* __restrict__ Wdir,
                            const float* __restrict__ bact,
                            const float* __restrict__ blab,
                            const float* __restrict__ bdir) {
    int i = blockIdx.x * blockDim.x + threadIdx.x;
    int stride = gridDim.x * blockDim.x;
    for (int e = i; e < 768 * 200; e += stride) {
        int k = e / 200, j = e % 200;
        g_WtProj[e] = Wproj[j * 768 + k];
    }
    for (int e = i; e < 100 * 500; e += stride) {
        int c = e / 500, r = e % 500;
        g_WtE[e] = Wtree[r * 200 + 100 + c];
    }
    for (int e = i; e < 600 * 24; e += stride) {
        int c = e / 24, q = e % 24;
        float v;
        if (q < 2)       v = Wact[q * 600 + c];
        else if (q < 21) v = Wlab[(q - 2) * 600 + c];
        else             v = Wdir[(q - 21) * 600 + c];
        g_WL[e] = v;
    }
    if (i < 24) {
        g_bL[i] = (i < 2) ? bact[i] : (i < 21) ? blab[i - 2] : bdir[i - 21];
    }
}

// ---------------- generic fp32 GEMM: C[M,N] = A[M,lda] * B[K,N] + bias ----------------
__global__ void gemm_kernel(const float* __restrict__ A, int lda,
                            const float* __restrict__ B,
                            const float* __restrict__ bias,
                            float* __restrict__ C, int ldc,
                            int N, int K) {
    __shared__ float As[16][68];
    __shared__ float Bs[16][64];
    int m0 = blockIdx.y * 64;
    int n0 = blockIdx.x * 64;
    int tid = threadIdx.x;
    int r0 = (tid >> 3) * 4;
    int c0 = (tid & 7) * 8;
    float acc[4][8];
    #pragma unroll
    for (int i = 0; i < 4; i++)
        #pragma unroll
        for (int j = 0; j < 8; j++) acc[i][j] = 0.f;

    for (int k0 = 0; k0 < K; k0 += 16) {
        #pragma unroll
        for (int i = 0; i < 8; i++) {
            int e = tid + 128 * i;
            int m = e >> 4, k = e & 15;
            As[k][m] = (k0 + k < K) ? A[(m0 + m) * lda + k0 + k] : 0.f;
        }
        #pragma unroll
        for (int i = 0; i < 8; i++) {
            int e = tid + 128 * i;
            int k = e >> 6, n = e & 63;
            float v = 0.f;
            if (k0 + k < K && n0 + n < N) v = B[(k0 + k) * N + n0 + n];
            Bs[k][n] = v;
        }
        __syncthreads();
        #pragma unroll
        for (int kk = 0; kk < 16; kk++) {
            float a[4];
            #pragma unroll
            for (int i = 0; i < 4; i++) a[i] = As[kk][r0 + i];
            float4 b0 = *(const float4*)&Bs[kk][c0];
            float4 b1 = *(const float4*)&Bs[kk][c0 + 4];
            float b[8] = {b0.x, b0.y, b0.z, b0.w, b1.x, b1.y, b1.z, b1.w};
            #pragma unroll
            for (int i = 0; i < 4; i++)
                #pragma unroll
                for (int j = 0; j < 8; j++) acc[i][j] += a[i] * b[j];
        }
        __syncthreads();
    }
    #pragma unroll
    for (int i = 0; i < 4; i++) {
        int m = m0 + r0 + i;
        #pragma unroll
        for (int j = 0; j < 8; j++) {
            int n = n0 + c0 + j;
            if (n < N) C[m * ldc + n] = acc[i][j] + bias[n];
        }
    }
}

// ---------------- copy c_e into the packed PC rows ----------------
__global__ void copyc_kernel() {
    int i = blockIdx.x * blockDim.x + threadIdx.x;
    int stride = gridDim.x * blockDim.x;
    for (int e = i; e < NE * 25; e += stride) {
        int m = e / 25, q = e % 25;
        const float4* src = (const float4*)(g_encp + (size_t)m * 200 + 100);
        float4* dst = (float4*)(g_PC + (size_t)m * 640 + 512);
        dst[q] = src[q];
    }
}

// ---------------- sequential TreeLSTM chain (single CTA, pipelined) ----------------
// h stored in 4 segments of 28 floats (25 used + pad): segment q = cols [25q, 25q+25),
// base offset 28q floats (112B, 16B-aligned) -> all LDS.64 aligned.
// Threads 0..999: thread t: row pair g = t>>2 (rows 2g, 2g+1), col quarter q = t&3.
//   Each h chunk loaded ONCE (12 LDS.64 + 1 LDS.32) and reused for both rows.
//   4-thread shuffle reduction per row pair, STS.64 into gs.
// Threads 1000..1023: cp.async prefetch of PC row m+2 into 3-slot SMEM ring.
// Threads 0..99 apply gates (MUFU.TANH-based).
__global__ void __launch_bounds__(1024, 1) chain_kernel(const float* __restrict__ Wtree) {
    __shared__ __align__(16) float hs[4 * 28];
    __shared__ __align__(16) float gs[504];
    __shared__ __align__(16) float psm[3][640];
    int tid = threadIdx.x;
    int g = tid >> 2;      // row pair 0..249 (tid<1000)
    int q = tid & 3;       // col quarter

    // weights: rows 2g, 2g+1, cols [25q, 25q+25): 12 f32x2 pairs + 1 scalar per row
    unsigned long long w2[2][12];
    float wo[2];
    if (tid < 1000) {
        #pragma unroll
        for (int rr = 0; rr < 2; rr++) {
            const float* wb = Wtree + (size_t)(2 * g + rr) * 200 + 25 * q;
            #pragma unroll
            for (int c = 0; c < 12; c++) {
                float lo = wb[2 * c], hi = wb[2 * c + 1];
                w2[rr][c] = ((unsigned long long)__float_as_uint(hi) << 32) | __float_as_uint(lo);
            }
            wo[rr] = wb[24];
        }
    } else {
        #pragma unroll
        for (int rr = 0; rr < 2; rr++) {
            #pragma unroll
            for (int c = 0; c < 12; c++) w2[rr][c] = 0ull;
            wo[rr] = 0.f;
        }
    }

    float cprev = 0.f;
    if (tid < 100) {
        float h0 = g_encp[tid];
        cprev = g_encp[100 + tid];
        hs[(tid / 25) * 28 + (tid % 25)] = h0;
        g_X[tid] = h0;
        g_X[100 + tid] = cprev;
    }
    if (tid >= 100 && tid < 104) hs[(tid - 100) * 28 + 25] = 0.f;  // pads (never rewritten)

    // prologue: prefetch PC rows 1 and 2
    if (tid >= 1000) {
        int p = tid - 1000;
        #pragma unroll
        for (int s = 1; s <= 2; s++) {
            const float4* src = (const float4*)(g_PC + (size_t)s * 640);
            unsigned sdst = (unsigned)__cvta_generic_to_shared(&psm[s % 3][0]);
            for (int k = p; k < 160; k += 24) {
                asm volatile("cp.async.cg.shared.global [%0], [%1], 16;\n"
                             :: "r"(sdst + k * 16), "l"(src + k) : "memory");
            }
            asm volatile("cp.async.commit_group;\n" ::: "memory");
        }
    }
    __syncthreads();

    for (int m = 1; m <= NE - 2; m++) {
        if (tid >= 1000) {
            int p = tid - 1000;
            int mp = m + 2;
            if (mp < NE) {
                const float4* src = (const float4*)(g_PC + (size_t)mp * 640);
                unsigned sdst = (unsigned)__cvta_generic_to_shared(&psm[mp % 3][0]);
                for (int k = p; k < 160; k += 24) {
                    asm volatile("cp.async.cg.shared.global [%0], [%1], 16;\n"
                                 :: "r"(sdst + k * 16), "l"(src + k) : "memory");
                }
            }
            asm volatile("cp.async.commit_group;\n" ::: "memory");
            asm volatile("cp.async.wait_group 2;\n" ::: "memory");
        } else {
            const float* hb = hs + 28 * q;
            unsigned long long a0 = 0ull, a1 = 0ull;
            #pragma unroll
            for (int c = 0; c < 12; c++) {
                unsigned long long hv = *(const unsigned long long*)(hb + 2 * c);
                FMA2(a0, w2[0][c], hv);
                FMA2(a1, w2[1][c], hv);
            }
            float h24 = hb[24];
            float s0 = __uint_as_float((unsigned)a0) + __uint_as_float((unsigned)(a0 >> 32))
                     + wo[0] * h24;
            float s1 = __uint_as_float((unsigned)a1) + __uint_as_float((unsigned)(a1 >> 32))
                     + wo[1] * h24;
            unsigned mask = (tid < 992) ? 0xffffffffu : 0x000000ffu;
            s0 += __shfl_xor_sync(mask, s0, 1);
            s1 += __shfl_xor_sync(mask, s1, 1);
            s0 += __shfl_xor_sync(mask, s0, 2);
            s1 += __shfl_xor_sync(mask, s1, 2);
            if (q == 0) *(float2*)(gs + 2 * g) = make_float2(s0, s1);
        }
        __syncthreads();
        if (tid < 100) {
            const float* P = psm[m % 3];
            float gi  = gs[tid]       + P[tid];
            float gf1 = gs[100 + tid] + P[100 + tid];
            float gf2 = gs[200 + tid] + P[200 + tid];
            float go  = gs[300 + tid] + P[300 + tid];
            float gu  = gs[400 + tid] + P[400 + tid];
            float ce2 = P[512 + tid];
            float cc = sig_t(gi) * __tanhf(gu) + sig_t(gf1) * cprev + sig_t(gf2) * ce2;
            float hh = sig_t(go) * __tanhf(cc);
            cprev = cc;
            hs[(tid / 25) * 28 + (tid % 25)] = hh;
            float* Xm = g_X + (size_t)m * 200;
            Xm[tid] = hh;
            Xm[100 + tid] = cc;
        }
        __syncthreads();
    }
}

// ---------------- per-step losses (parallel) ----------------
__device__ __forceinline__ float ce_all(const float* l, int a, int lb, int dr) {
    float m0 = fmaxf(l[0], l[1]);
    float loss = m0 + __logf(__expf(l[0] - m0) + __expf(l[1] - m0)) - l[a];
    float m1 = l[2];
    #pragma unroll
    for (int q = 3; q < 21; q++) m1 = fmaxf(m1, l[q]);
    float s1 = 0.f;
    #pragma unroll
    for (int q = 2; q < 21; q++) s1 += __expf(l[q] - m1);
    loss += m1 + __logf(s1) - l[2 + lb];
    float m2 = fmaxf(fmaxf(l[21], l[22]), l[23]);
    float s2 = __expf(l[21] - m2) + __expf(l[22] - m2) + __expf(l[23] - m2);
    loss += m2 + __logf(s2) - l[21 + dr];
    return loss;
}

__global__ void loss_kernel(const float* __restrict__ missing,
                            const int* __restrict__ ga,
                            const int* __restrict__ gl,
                            const int* __restrict__ gd) {
    __shared__ float fs[16][600];
    int t0 = blockIdx.x * 16;
    int tid = threadIdx.x;

    for (int e = tid; e < 16 * 600; e += 256) {
        int s = e / 600, c = e % 600;
        int t = t0 + s;
        float v = 0.f;
        if (t < NSTEP) {
            const float* src;
            int base;
            if (c < 200) {          // s1
                base = 0;
                if ((t & 1) == 0 && t >= 2) src = g_X + (size_t)(t / 2 - 1) * 200;
                else                         src = missing;
            } else if (c < 400) {   // s0
                base = 200;
                if (t & 1)       src = g_X + (size_t)(t / 2) * 200;
                else             src = (t == 0) ? missing : (g_encp + (size_t)(t / 2) * 200);
            } else {                // b
                base = 400;
                if (t == 0) src = g_encp;
                else {
                    int idx = t / 2 + 1;
                    src = (idx < NE) ? (g_encp + (size_t)idx * 200) : missing;
                }
            }
            v = src[c - base];
        }
        fs[s][c] = v;
    }
    __syncthreads();

    int warp = tid >> 5, lane = tid & 31;
    const float* f0 = fs[warp * 2];
    const float* f1 = fs[warp * 2 + 1];
    float acc0[24], acc1[24];
    #pragma unroll
    for (int q = 0; q < 24; q++) { acc0[q] = 0.f; acc1[q] = 0.f; }

    for (int c = lane; c < 600; c += 32) {
        float fa = f0[c], fb = f1[c];
        const float4* wp = (const float4*)(g_WL + c * 24);
        #pragma unroll
        for (int v4 = 0; v4 < 6; v4++) {
            float4 wv = wp[v4];
            acc0[v4 * 4 + 0] += wv.x * fa;  acc1[v4 * 4 + 0] += wv.x * fb;
            acc0[v4 * 4 + 1] += wv.y * fa;  acc1[v4 * 4 + 1] += wv.y * fb;
            acc0[v4 * 4 + 2] += wv.z * fa;  acc1[v4 * 4 + 2] += wv.z * fb;
            acc0[v4 * 4 + 3] += wv.w * fa;  acc1[v4 * 4 + 3] += wv.w * fb;
        }
    }
    #pragma unroll
    for (int off = 16; off; off >>= 1) {
        #pragma unroll
        for (int q = 0; q < 24; q++) {
            acc0[q] += __shfl_xor_sync(0xffffffffu, acc0[q], off);
            acc1[q] += __shfl_xor_sync(0xffffffffu, acc1[q], off);
        }
    }
    if (lane == 0) {
        int ta = t0 + warp * 2;
        if (ta < NSTEP) {
            float l[24];
            #pragma unroll
            for (int q = 0; q < 24; q++) l[q] = acc0[q] + g_bL[q];
            g_losses[ta] = ce_all(l, ga[ta], gl[ta], gd[ta]);
        }
        int tb = ta + 1;
        if (tb < NSTEP) {
            float l[24];
            #pragma unroll
            for (int q = 0; q < 24; q++) l[q] = acc1[q] + g_bL[q];
            g_losses[tb] = ce_all(l, ga[tb], gl[tb], gd[tb]);
        }
    }
}

// ---------------- deterministic final reduction ----------------
__global__ void reduce_kernel(float* __restrict__ out) {
    __shared__ float ss[1024];
    float s = 0.f;
    for (int i = threadIdx.x; i < NSTEP; i += 1024) s += g_losses[i];
    ss[threadIdx.x] = s;
    __syncthreads();
    for (int o = 512; o; o >>= 1) {
        if (threadIdx.x < o) ss[threadIdx.x] += ss[threadIdx.x + o];
        __syncthreads();
    }
    if (threadIdx.x == 0) out[0] = ss[0];
}

// ---------------- launch ----------------
extern "C" void kernel_launch(void* const* d_in, const int* in_sizes, int n_in,
                              void* d_out, int out_size) {
    const float* enc_cls = (const float*)d_in[0];
    const float* W_proj  = (const float*)d_in[1];
    const float* b_proj  = (const float*)d_in[2];
    const float* missing = (const float*)d_in[3];
    const float* W_act   = (const float*)d_in[4];
    const float* b_act   = (const float*)d_in[5];
    const float* W_lab   = (const float*)d_in[6];
    const float* b_lab   = (const float*)d_in[7];
    const float* W_dir   = (const float*)d_in[8];
    const float* b_dir   = (const float*)d_in[9];
    const float* W_tree  = (const float*)d_in[10];
    const float* b_tree  = (const float*)d_in[11];
    const int*   ga      = (const int*)d_in[12];
    const int*   gl      = (const int*)d_in[13];
    const int*   gd      = (const int*)d_in[14];

    void *p_encp, *p_PC, *p_WtProj, *p_WtE;
    cudaGetSymbolAddress(&p_encp, g_encp);
    cudaGetSymbolAddress(&p_PC, g_PC);
    cudaGetSymbolAddress(&p_WtProj, g_WtProj);
    cudaGetSymbolAddress(&p_WtE, g_WtE);

    prep_kernel<<<128, 256>>>(W_proj, W_tree, W_act, W_lab, W_dir, b_act, b_lab, b_dir);

    // enc_proj = enc_cls @ W_proj^T + b_proj   (M=32768, N=200, K=768)
    gemm_kernel<<<dim3(4, 512), 128>>>(enc_cls, 768, (const float*)p_WtProj,
                                       b_proj, (float*)p_encp, 200, 200, 768);

    // P = enc_proj[:, :100] @ W_e^T + b_tree   (M=32768, N=500, K=100) -> packed rows
    gemm_kernel<<<dim3(8, 512), 128>>>((const float*)p_encp, 200, (const float*)p_WtE,
                                       b_tree, (float*)p_PC, 640, 500, 100);

    copyc_kernel<<<256, 256>>>();

    chain_kernel<<<1, 1024>>>(W_tree);

    loss_kernel<<<4096, 256>>>(missing, ga, gl, gd);

    reduce_kernel<<<1, 1024>>>((float*)d_out);
}

// round 5
// speedup vs baseline: 1.5103x; 1.0048x over previous
#include <cuda_runtime.h>
#include <cuda_bf16.h>
#include <math.h>

#define NE 32768
#define NSTEP 65535   // 2*NE - 1

// ---------------- device scratch (static, no allocation) ----------------
__device__ __align__(16) float g_encp[NE * 200];      // projected encodings (h|c)
__device__ __align__(16) float g_PC[NE * 640];        // per-row: [0..512)=P (CTA-major perm), [512..640)=c_e slices
__device__ __align__(16) float g_X[NE * 200];         // merge chain states (h|c)
__device__ __align__(16) float g_WtProj[768 * 200];   // W_proj transposed
__device__ __align__(16) float g_WtE[100 * 512];      // W_tree[:,100:200] transposed + column-permuted (CTA-major)
__device__ __align__(16) float g_btE[512];            // b_tree permuted to match
__device__ __align__(16) float g_WL[600 * 24];        // concat loss weights, [col][out]
__device__ float g_bL[24];
__device__ float g_losses[NSTEP];

__device__ __forceinline__ float sig_t(float x)  { return 0.5f * __tanhf(0.5f * x) + 0.5f; }

#define FMA2(acc, a, b) asm("fma.rn.f32x2 %0, %1, %2, %0;" : "+l"(acc) : "l"(a), "l"(b))

// P column permutation: W row R = 100k + j (j = hidden unit 0..99)
//   r = j/50, u = j%50  ->  col' = 256*r + 50*k + u   (pads at [250,256) and [506,512))
// c_e slice: unit j -> 512 + (j/50)*64 + j%50

// ---------------- prep: transposes / packing ----------------
__global__ void prep_kernel(const float* __restrict__ Wproj,
                            const float* __restrict__ Wtree,
                            const float* __restrict__ btree,
                            const float* __restrict__ Wact,
                            const float* __restrict__ Wlab,
                            const float* __restrict__ Wdir,
                            const float* __restrict__ bact,
                            const float* __restrict__ blab,
                            const float* __restrict__ bdir) {
    int i = blockIdx.x * blockDim.x + threadIdx.x;
    int stride = gridDim.x * blockDim.x;
    for (int e = i; e < 768 * 200; e += stride) {
        int k = e / 200, j = e % 200;
        g_WtProj[e] = Wproj[j * 768 + k];
    }
    for (int e = i; e < 100 * 512; e += stride) {
        int c = e / 512, cp = e % 512;
        int r = cp >> 8, rem = cp & 255;
        float v = 0.f;
        if (rem < 250) {
            int k = rem / 50, u = rem % 50;
            int R = 100 * k + 50 * r + u;
            v = Wtree[R * 200 + 100 + c];
        }
        g_WtE[e] = v;
    }
    if (i < 512) {
        int r = i >> 8, rem = i & 255;
        float v = 0.f;
        if (rem < 250) {
            int k = rem / 50, u = rem % 50;
            v = btree[100 * k + 50 * r + u];
        }
        g_btE[i] = v;
    }
    for (int e = i; e < 600 * 24; e += stride) {
        int c = e / 24, q = e % 24;
        float v;
        if (q < 2)       v = Wact[q * 600 + c];
        else if (q < 21) v = Wlab[(q - 2) * 600 + c];
        else             v = Wdir[(q - 21) * 600 + c];
        g_WL[e] = v;
    }
    if (i < 24) {
        g_bL[i] = (i < 2) ? bact[i] : (i < 21) ? blab[i - 2] : bdir[i - 21];
    }
}

// ---------------- generic fp32 GEMM: C[M,N] = A[M,lda] * B[K,N] + bias ----------------
__global__ void gemm_kernel(const float* __restrict__ A, int lda,
                            const float* __restrict__ B,
                            const float* __restrict__ bias,
                            float* __restrict__ C, int ldc,
                            int N, int K) {
    __shared__ float As[16][68];
    __shared__ float Bs[16][64];
    int m0 = blockIdx.y * 64;
    int n0 = blockIdx.x * 64;
    int tid = threadIdx.x;
    int r0 = (tid >> 3) * 4;
    int c0 = (tid & 7) * 8;
    float acc[4][8];
    #pragma unroll
    for (int i = 0; i < 4; i++)
        #pragma unroll
        for (int j = 0; j < 8; j++) acc[i][j] = 0.f;

    for (int k0 = 0; k0 < K; k0 += 16) {
        #pragma unroll
        for (int i = 0; i < 8; i++) {
            int e = tid + 128 * i;
            int m = e >> 4, k = e & 15;
            As[k][m] = (k0 + k < K) ? A[(m0 + m) * lda + k0 + k] : 0.f;
        }
        #pragma unroll
        for (int i = 0; i < 8; i++) {
            int e = tid + 128 * i;
            int k = e >> 6, n = e & 63;
            float v = 0.f;
            if (k0 + k < K && n0 + n < N) v = B[(k0 + k) * N + n0 + n];
            Bs[k][n] = v;
        }
        __syncthreads();
        #pragma unroll
        for (int kk = 0; kk < 16; kk++) {
            float a[4];
            #pragma unroll
            for (int i = 0; i < 4; i++) a[i] = As[kk][r0 + i];
            float4 b0 = *(const float4*)&Bs[kk][c0];
            float4 b1 = *(const float4*)&Bs[kk][c0 + 4];
            float b[8] = {b0.x, b0.y, b0.z, b0.w, b1.x, b1.y, b1.z, b1.w};
            #pragma unroll
            for (int i = 0; i < 4; i++)
                #pragma unroll
                for (int j = 0; j < 8; j++) acc[i][j] += a[i] * b[j];
        }
        __syncthreads();
    }
    #pragma unroll
    for (int i = 0; i < 4; i++) {
        int m = m0 + r0 + i;
        #pragma unroll
        for (int j = 0; j < 8; j++) {
            int n = n0 + c0 + j;
            if (n < N) C[m * ldc + n] = acc[i][j] + bias[n];
        }
    }
}

// ---------------- copy c_e into the packed PC rows (permuted slices) ----------------
__global__ void copyc_kernel() {
    int i = blockIdx.x * blockDim.x + threadIdx.x;
    int stride = gridDim.x * blockDim.x;
    for (int e = i; e < NE * 100; e += stride) {
        int m = e / 100, j = e % 100;
        g_PC[(size_t)m * 640 + 512 + (j / 50) * 64 + (j % 50)] = g_encp[(size_t)m * 200 + 100 + j];
    }
}

// ---------------- sequential TreeLSTM chain: 2-CTA cluster ----------------
// CTA r owns hidden units [50r, 50r+50): matvec rows R = 100k + 50r + u (250 rows),
// gates for its 50 units, publishes its h-half to the peer via DSMEM.
// Threads 0..499: matvec, pair g = t>>2 (local rows 2g,2g+1), col quarter q = t&3.
//   Col quarter q covers units [25q,25q+25): foreign iff (q>>1) != rank.
// Threads 0..49: gate phase for unit j = 50*rank + tid.
// Threads 512..543: cp.async prefetch of this CTA's PC slice (m+2) into 3-slot ring.
__global__ void __launch_bounds__(544, 1) __cluster_dims__(2, 1, 1)
chain_kernel(const float* __restrict__ Wtree) {
    __shared__ __align__(16) float hs[2][112];     // h double buffer: unit j -> (j/25)*28 + j%25
    __shared__ __align__(16) float gs[252];        // local matvec results (lr = 50k+u)
    __shared__ __align__(16) float psm[3][320];    // [0..256)=P slice, [256..308)=c slice
    __shared__ __align__(8) unsigned long long mbar[2];
    int tid = threadIdx.x;
    unsigned rank;
    asm("mov.u32 %0, %%cluster_ctarank;" : "=r"(rank));
    unsigned peer = rank ^ 1u;
    int g = tid >> 2, q = tid & 3;

    // --- weights: local rows lr0=2g, lr0+1 -> W rows 100k + 50*rank + u ---
    unsigned long long w2[2][12];
    float wo[2];
    if (tid < 500) {
        int lr0 = 2 * g;
        int k = lr0 / 50, u0 = lr0 % 50;
        int R0 = 100 * k + 50 * (int)rank + u0;
        #pragma unroll
        for (int rr = 0; rr < 2; rr++) {
            const float* wb = Wtree + (size_t)(R0 + rr) * 200 + 25 * q;
            #pragma unroll
            for (int c = 0; c < 12; c++) {
                float lo = wb[2 * c], hi = wb[2 * c + 1];
                w2[rr][c] = ((unsigned long long)__float_as_uint(hi) << 32) | __float_as_uint(lo);
            }
            wo[rr] = wb[24];
        }
    } else {
        #pragma unroll
        for (int rr = 0; rr < 2; rr++) {
            #pragma unroll
            for (int c = 0; c < 12; c++) w2[rr][c] = 0ull;
            wo[rr] = 0.f;
        }
    }

    // --- mbar init (count = 50 arrivals per phase) ---
    if (tid == 0) {
        unsigned a0 = (unsigned)__cvta_generic_to_shared(&mbar[0]);
        unsigned a1 = (unsigned)__cvta_generic_to_shared(&mbar[1]);
        asm volatile("mbarrier.init.shared.b64 [%0], %1;" :: "r"(a0), "r"(50) : "memory");
        asm volatile("mbarrier.init.shared.b64 [%0], %1;" :: "r"(a1), "r"(50) : "memory");
    }

    // --- h0 = enc[0] into buffer 0 (both CTAs, full vector) ---
    if (tid < 100) {
        hs[0][(tid / 25) * 28 + (tid % 25)] = g_encp[tid];
        if (rank == 0) {
            g_X[tid] = g_encp[tid];
            g_X[100 + tid] = g_encp[100 + tid];
        }
    }

    float cprev = 0.f;
    if (tid < 50) cprev = g_encp[100 + 50 * (int)rank + tid];

    // --- remote addresses for gate threads ---
    unsigned rh[2], rmb[2];
    if (tid < 50) {
        int j = 50 * (int)rank + tid;
        int slot = (j / 25) * 28 + (j % 25);
        unsigned l0 = (unsigned)__cvta_generic_to_shared(&hs[0][slot]);
        unsigned l1 = (unsigned)__cvta_generic_to_shared(&hs[1][slot]);
        unsigned m0a = (unsigned)__cvta_generic_to_shared(&mbar[0]);
        unsigned m1a = (unsigned)__cvta_generic_to_shared(&mbar[1]);
        asm("mapa.shared::cluster.u32 %0, %1, %2;" : "=r"(rh[0]) : "r"(l0), "r"(peer));
        asm("mapa.shared::cluster.u32 %0, %1, %2;" : "=r"(rh[1]) : "r"(l1), "r"(peer));
        asm("mapa.shared::cluster.u32 %0, %1, %2;" : "=r"(rmb[0]) : "r"(m0a), "r"(peer));
        asm("mapa.shared::cluster.u32 %0, %1, %2;" : "=r"(rmb[1]) : "r"(m1a), "r"(peer));
    }
    unsigned lmb[2];
    lmb[0] = (unsigned)__cvta_generic_to_shared(&mbar[0]);
    lmb[1] = (unsigned)__cvta_generic_to_shared(&mbar[1]);

    // --- prologue prefetch: PC slices for m=1,2 ---
    if (tid >= 512) {
        int p = tid - 512;
        #pragma unroll
        for (int s = 1; s <= 2; s++) {
            const float4* base = (const float4*)(g_PC + (size_t)s * 640);
            unsigned sdst = (unsigned)__cvta_generic_to_shared(&psm[s % 3][0]);
            for (int k4 = p; k4 < 77; k4 += 32) {
                const float4* src; unsigned dst;
                if (k4 < 64) { src = base + 64 * rank + k4;            dst = sdst + k4 * 16; }
                else         { src = base + 128 + 16 * rank + (k4-64); dst = sdst + 1024 + (k4-64) * 16; }
                asm volatile("cp.async.cg.shared.global [%0], [%1], 16;\n" :: "r"(dst), "l"(src) : "memory");
            }
            asm volatile("cp.async.commit_group;\n" ::: "memory");
        }
    }
    __syncthreads();
    // cluster sync: mbar init must be visible before peer arrivals
    asm volatile("barrier.cluster.arrive.aligned;" ::: "memory");
    asm volatile("barrier.cluster.wait.aligned;" ::: "memory");

    bool foreign = ((q >> 1) != (int)rank);

    for (int m = 1; m <= NE - 2; m++) {
        if (tid >= 512) {
            int p = tid - 512;
            int mp = m + 2;
            if (mp < NE) {
                const float4* base = (const float4*)(g_PC + (size_t)mp * 640);
                unsigned sdst = (unsigned)__cvta_generic_to_shared(&psm[mp % 3][0]);
                for (int k4 = p; k4 < 77; k4 += 32) {
                    const float4* src; unsigned dst;
                    if (k4 < 64) { src = base + 64 * rank + k4;            dst = sdst + k4 * 16; }
                    else         { src = base + 128 + 16 * rank + (k4-64); dst = sdst + 1024 + (k4-64) * 16; }
                    asm volatile("cp.async.cg.shared.global [%0], [%1], 16;\n" :: "r"(dst), "l"(src) : "memory");
                }
            }
            asm volatile("cp.async.commit_group;\n" ::: "memory");
            asm volatile("cp.async.wait_group 2;\n" ::: "memory");
        } else if (tid < 500) {
            // wait for peer's h-half (only foreign column quarters)
            if (m >= 2 && foreign) {
                unsigned addr = lmb[(m - 1) & 1];
                unsigned parity = ((unsigned)(m - 2) >> 1) & 1u;
                unsigned done;
                asm volatile("{\n\t.reg .pred p;\n\t"
                             "mbarrier.try_wait.parity.acquire.cluster.shared::cta.b64 p, [%1], %2;\n\t"
                             "selp.b32 %0, 1, 0, p;\n\t}"
                             : "=r"(done) : "r"(addr), "r"(parity) : "memory");
                while (!done) {
                    asm volatile("{\n\t.reg .pred p;\n\t"
                                 "mbarrier.try_wait.parity.acquire.cluster.shared::cta.b64 p, [%1], %2;\n\t"
                                 "selp.b32 %0, 1, 0, p;\n\t}"
                                 : "=r"(done) : "r"(addr), "r"(parity) : "memory");
                }
            }
            const float* hb = hs[(m - 1) & 1] + 28 * q;
            unsigned long long a0 = 0ull, a1 = 0ull;
            #pragma unroll
            for (int c = 0; c < 12; c++) {
                unsigned long long hv = *(const unsigned long long*)(hb + 2 * c);
                FMA2(a0, w2[0][c], hv);
                FMA2(a1, w2[1][c], hv);
            }
            float h24 = hb[24];
            float s0 = __uint_as_float((unsigned)a0) + __uint_as_float((unsigned)(a0 >> 32))
                     + wo[0] * h24;
            float s1 = __uint_as_float((unsigned)a1) + __uint_as_float((unsigned)(a1 >> 32))
                     + wo[1] * h24;
            unsigned mask = (tid < 480) ? 0xffffffffu : 0x000fffffu;
            s0 += __shfl_xor_sync(mask, s0, 1);
            s1 += __shfl_xor_sync(mask, s1, 1);
            s0 += __shfl_xor_sync(mask, s0, 2);
            s1 += __shfl_xor_sync(mask, s1, 2);
            if (q == 0) *(float2*)(gs + 2 * g) = make_float2(s0, s1);
        }
        __syncthreads();
        if (tid < 50) {
            const float* P = psm[m % 3];
            float gi  = gs[tid]       + P[tid];
            float gf1 = gs[50 + tid]  + P[50 + tid];
            float gf2 = gs[100 + tid] + P[100 + tid];
            float go  = gs[150 + tid] + P[150 + tid];
            float gu  = gs[200 + tid] + P[200 + tid];
            float ce2 = P[256 + tid];
            float cc = sig_t(gi) * __tanhf(gu) + sig_t(gf1) * cprev + sig_t(gf2) * ce2;
            float hh = sig_t(go) * __tanhf(cc);
            cprev = cc;
            int b = m & 1;
            int j = 50 * (int)rank + tid;
            hs[b][(j / 25) * 28 + (j % 25)] = hh;
            // publish to peer + signal
            asm volatile("st.shared::cluster.f32 [%0], %1;" :: "r"(rh[b]), "f"(hh) : "memory");
            asm volatile("mbarrier.arrive.release.cluster.shared::cluster.b64 _, [%0];"
                         :: "r"(rmb[b]) : "memory");
            float* Xm = g_X + (size_t)m * 200;
            Xm[j] = hh;
            Xm[100 + j] = cc;
        }
        __syncthreads();
    }

    // no CTA exits while peer's DSMEM traffic may be in flight
    asm volatile("barrier.cluster.arrive.aligned;" ::: "memory");
    asm volatile("barrier.cluster.wait.aligned;" ::: "memory");
}

// ---------------- per-step losses (parallel) ----------------
__device__ __forceinline__ float ce_all(const float* l, int a, int lb, int dr) {
    float m0 = fmaxf(l[0], l[1]);
    float loss = m0 + __logf(__expf(l[0] - m0) + __expf(l[1] - m0)) - l[a];
    float m1 = l[2];
    #pragma unroll
    for (int q = 3; q < 21; q++) m1 = fmaxf(m1, l[q]);
    float s1 = 0.f;
    #pragma unroll
    for (int q = 2; q < 21; q++) s1 += __expf(l[q] - m1);
    loss += m1 + __logf(s1) - l[2 + lb];
    float m2 = fmaxf(fmaxf(l[21], l[22]), l[23]);
    float s2 = __expf(l[21] - m2) + __expf(l[22] - m2) + __expf(l[23] - m2);
    loss += m2 + __logf(s2) - l[21 + dr];
    return loss;
}

__global__ void loss_kernel(const float* __restrict__ missing,
                            const int* __restrict__ ga,
                            const int* __restrict__ gl,
                            const int* __restrict__ gd) {
    __shared__ float fs[16][600];
    int t0 = blockIdx.x * 16;
    int tid = threadIdx.x;

    for (int e = tid; e < 16 * 600; e += 256) {
        int s = e / 600, c = e % 600;
        int t = t0 + s;
        float v = 0.f;
        if (t < NSTEP) {
            const float* src;
            int base;
            if (c < 200) {          // s1
                base = 0;
                if ((t & 1) == 0 && t >= 2) src = g_X + (size_t)(t / 2 - 1) * 200;
                else                         src = missing;
            } else if (c < 400) {   // s0
                base = 200;
                if (t & 1)       src = g_X + (size_t)(t / 2) * 200;
                else             src = (t == 0) ? missing : (g_encp + (size_t)(t / 2) * 200);
            } else {                // b
                base = 400;
                if (t == 0) src = g_encp;
                else {
                    int idx = t / 2 + 1;
                    src = (idx < NE) ? (g_encp + (size_t)idx * 200) : missing;
                }
            }
            v = src[c - base];
        }
        fs[s][c] = v;
    }
    __syncthreads();

    int warp = tid >> 5, lane = tid & 31;
    const float* f0 = fs[warp * 2];
    const float* f1 = fs[warp * 2 + 1];
    float acc0[24], acc1[24];
    #pragma unroll
    for (int q = 0; q < 24; q++) { acc0[q] = 0.f; acc1[q] = 0.f; }

    for (int c = lane; c < 600; c += 32) {
        float fa = f0[c], fb = f1[c];
        const float4* wp = (const float4*)(g_WL + c * 24);
        #pragma unroll
        for (int v4 = 0; v4 < 6; v4++) {
            float4 wv = wp[v4];
            acc0[v4 * 4 + 0] += wv.x * fa;  acc1[v4 * 4 + 0] += wv.x * fb;
            acc0[v4 * 4 + 1] += wv.y * fa;  acc1[v4 * 4 + 1] += wv.y * fb;
            acc0[v4 * 4 + 2] += wv.z * fa;  acc1[v4 * 4 + 2] += wv.z * fb;
            acc0[v4 * 4 + 3] += wv.w * fa;  acc1[v4 * 4 + 3] += wv.w * fb;
        }
    }
    #pragma unroll
    for (int off = 16; off; off >>= 1) {
        #pragma unroll
        for (int q = 0; q < 24; q++) {
            acc0[q] += __shfl_xor_sync(0xffffffffu, acc0[q], off);
            acc1[q] += __shfl_xor_sync(0xffffffffu, acc1[q], off);
        }
    }
    if (lane == 0) {
        int ta = t0 + warp * 2;
        if (ta < NSTEP) {
            float l[24];
            #pragma unroll
            for (int q = 0; q < 24; q++) l[q] = acc0[q] + g_bL[q];
            g_losses[ta] = ce_all(l, ga[ta], gl[ta], gd[ta]);
        }
        int tb = ta + 1;
        if (tb < NSTEP) {
            float l[24];
            #pragma unroll
            for (int q = 0; q < 24; q++) l[q] = acc1[q] + g_bL[q];
            g_losses[tb] = ce_all(l, ga[tb], gl[tb], gd[tb]);
        }
    }
}

// ---------------- deterministic final reduction ----------------
__global__ void reduce_kernel(float* __restrict__ out) {
    __shared__ float ss[1024];
    float s = 0.f;
    for (int i = threadIdx.x; i < NSTEP; i += 1024) s += g_losses[i];
    ss[threadIdx.x] = s;
    __syncthreads();
    for (int o = 512; o; o >>= 1) {
        if (threadIdx.x < o) ss[threadIdx.x] += ss[threadIdx.x + o];
        __syncthreads();
    }
    if (threadIdx.x == 0) out[0] = ss[0];
}

// ---------------- launch ----------------
extern "C" void kernel_launch(void* const* d_in, const int* in_sizes, int n_in,
                              void* d_out, int out_size) {
    const float* enc_cls = (const float*)d_in[0];
    const float* W_proj  = (const float*)d_in[1];
    const float* b_proj  = (const float*)d_in[2];
    const float* missing = (const float*)d_in[3];
    const float* W_act   = (const float*)d_in[4];
    const float* b_act   = (const float*)d_in[5];
    const float* W_lab   = (const float*)d_in[6];
    const float* b_lab   = (const float*)d_in[7];
    const float* W_dir   = (const float*)d_in[8];
    const float* b_dir   = (const float*)d_in[9];
    const float* W_tree  = (const float*)d_in[10];
    const float* b_tree  = (const float*)d_in[11];
    const int*   ga      = (const int*)d_in[12];
    const int*   gl      = (const int*)d_in[13];
    const int*   gd      = (const int*)d_in[14];

    void *p_encp, *p_PC, *p_WtProj, *p_WtE, *p_btE;
    cudaGetSymbolAddress(&p_encp, g_encp);
    cudaGetSymbolAddress(&p_PC, g_PC);
    cudaGetSymbolAddress(&p_WtProj, g_WtProj);
    cudaGetSymbolAddress(&p_WtE, g_WtE);
    cudaGetSymbolAddress(&p_btE, g_btE);

    prep_kernel<<<128, 256>>>(W_proj, W_tree, b_tree, W_act, W_lab, W_dir,
                              b_act, b_lab, b_dir);

    // enc_proj = enc_cls @ W_proj^T + b_proj   (M=32768, N=200, K=768)
    gemm_kernel<<<dim3(4, 512), 128>>>(enc_cls, 768, (const float*)p_WtProj,
                                       b_proj, (float*)p_encp, 200, 200, 768);

    // P (CTA-major permuted cols) = enc_proj[:, :100] @ WtE' + btE'  (N=512, ldc=640)
    gemm_kernel<<<dim3(8, 512), 128>>>((const float*)p_encp, 200, (const float*)p_WtE,
                                       (const float*)p_btE, (float*)p_PC, 640, 512, 100);

    copyc_kernel<<<256, 256>>>();

    chain_kernel<<<2, 544>>>(W_tree);   // cluster (2,1,1) via __cluster_dims__

    loss_kernel<<<4096, 256>>>(missing, ga, gl, gd);

    reduce_kernel<<<1, 1024>>>((float*)d_out);
}